// round 2
// baseline (speedup 1.0000x reference)
#include <cuda_runtime.h>

// Occlusion_32220844654988
// out = sum_e exp(-|pos[dst_e] - pos[src_e]|) / NUM_GRAPHS
// (mean over ALL segments of a segment_sum == total sum / num_segments,
//  so batch_idx and the scatter are mathematically irrelevant.)
//
// NOTE: JAX x64 is disabled by default, so full_edge_index / batch_idx are
// int32 despite the reference saying int64.

#define N_EDGES_C 8388608
constexpr int THREADS = 256;
constexpr int BLOCKS = 2048;
// 2048 blocks * 256 threads * 16 edges/thread = 8,388,608 exactly.
constexpr int NTHREADS_TOTAL = THREADS * BLOCKS;

__device__ float g_partials[BLOCKS];

__global__ __launch_bounds__(THREADS) void occl_main_kernel(
    const float2* __restrict__ pos,
    const int* __restrict__ eidx)
{
    const int tid = blockIdx.x * blockDim.x + threadIdx.x;
    float acc = 0.0f;

    // 4 chunk-iterations, each chunk = 4 edges (one int4 per endpoint row).
    #pragma unroll 1
    for (int it = 0; it < 4; it++) {
        const int base = 4 * (tid + it * NTHREADS_TOTAL);

        int4 s = *reinterpret_cast<const int4*>(eidx + base);              // src row
        int4 d = *reinterpret_cast<const int4*>(eidx + N_EDGES_C + base);  // dst row

        int si[4] = {s.x, s.y, s.z, s.w};
        int di[4] = {d.x, d.y, d.z, d.w};

        float2 ps[4], pd[4];
        #pragma unroll
        for (int k = 0; k < 4; k++) ps[k] = pos[si[k]];
        #pragma unroll
        for (int k = 0; k < 4; k++) pd[k] = pos[di[k]];

        #pragma unroll
        for (int k = 0; k < 4; k++) {
            float dx = ps[k].x - pd[k].x;
            float dy = ps[k].y - pd[k].y;
            float d2 = fmaf(dx, dx, dy * dy);
            float eu;
            asm("sqrt.approx.f32 %0, %1;" : "=f"(eu) : "f"(d2));
            float t = -1.4426950408889634f * eu;   // -log2(e) * eu
            float r;
            asm("ex2.approx.f32 %0, %1;" : "=f"(r) : "f"(t));
            acc += r;
        }
    }

    // warp reduce
    #pragma unroll
    for (int o = 16; o > 0; o >>= 1)
        acc += __shfl_xor_sync(0xffffffffu, acc, o);

    __shared__ float ws[THREADS / 32];
    if ((threadIdx.x & 31) == 0) ws[threadIdx.x >> 5] = acc;
    __syncthreads();

    if (threadIdx.x < 32) {
        float v = (threadIdx.x < THREADS / 32) ? ws[threadIdx.x] : 0.0f;
        #pragma unroll
        for (int o = 4; o > 0; o >>= 1)
            v += __shfl_xor_sync(0xffffffffu, v, o);
        if (threadIdx.x == 0) g_partials[blockIdx.x] = v;
    }
}

__global__ __launch_bounds__(1024) void occl_reduce_kernel(float* __restrict__ out)
{
    __shared__ double sm[32];
    double v = 0.0;
    for (int i = threadIdx.x; i < BLOCKS; i += 1024)
        v += (double)g_partials[i];

    #pragma unroll
    for (int o = 16; o > 0; o >>= 1)
        v += __shfl_xor_sync(0xffffffffu, v, o);

    if ((threadIdx.x & 31) == 0) sm[threadIdx.x >> 5] = v;
    __syncthreads();

    if (threadIdx.x < 32) {
        double t = (threadIdx.x < 32) ? sm[threadIdx.x] : 0.0;
        #pragma unroll
        for (int o = 16; o > 0; o >>= 1)
            t += __shfl_xor_sync(0xffffffffu, t, o);
        if (threadIdx.x == 0)
            *out = (float)(t * (1.0 / 1024.0));   // / NUM_GRAPHS
    }
}

extern "C" void kernel_launch(void* const* d_in, const int* in_sizes, int n_in,
                              void* d_out, int out_size)
{
    const float2* pos  = (const float2*)d_in[0];  // node_pos [131072, 2] f32
    const int*    eidx = (const int*)d_in[1];     // full_edge_index [2, 8388608] i32
    // d_in[2] (batch_idx) is mathematically irrelevant — see header comment.
    (void)in_sizes; (void)n_in; (void)out_size;

    occl_main_kernel<<<BLOCKS, THREADS>>>(pos, eidx);
    occl_reduce_kernel<<<1, 1024>>>((float*)d_out);
}